// round 7
// baseline (speedup 1.0000x reference)
#include <cuda_runtime.h>

#define THREADS 224   // 7 warps: 196 patch threads + slack
#define NWARPS 7

// ---- 4-qubit helpers. mask = 8>>q (qubit 0 is MSB of the 4-bit index).
// Fully unrolled so masks are compile-time constants.

// General SU(2) gate: u00 = a+ib, u01 = c+id, u10 = -c+id, u11 = a-ib.
__device__ __forceinline__ void apply_su2(float* re, float* im, int mask,
                                          float a, float b, float c, float d) {
#pragma unroll
    for (int i = 0; i < 16; i++) {
        if (i & mask) continue;
        int j = i | mask;
        float r0 = re[i], i0 = im[i], r1 = re[j], i1 = im[j];
        re[i] =  a * r0 - b * i0 + c * r1 - d * i1;
        im[i] =  a * i0 + b * r0 + c * i1 + d * r1;
        re[j] = -c * r0 - d * i0 + a * r1 + b * i1;
        im[j] = -c * i0 + d * r0 + a * i1 - b * r1;
    }
}

__device__ __forceinline__ void apply_cnot(float* re, float* im, int mc, int mt) {
#pragma unroll
    for (int i = 0; i < 16; i++) {
        if ((i & mc) && !(i & mt)) {
            int j = i | mt;
            float tr = re[i]; re[i] = re[j]; re[j] = tr;
            float ti = im[i]; im[i] = im[j]; im[j] = ti;
        }
    }
}

__global__ __launch_bounds__(THREADS, 1)
void qnet_kernel(const float* __restrict__ x,       // [B,1,28,28]
                 const float* __restrict__ weight,  // [60]
                 const float* __restrict__ fc1_w,   // [64,784]
                 const float* __restrict__ fc1_b,   // [64]
                 const float* __restrict__ fc2_w,   // [10,64]
                 const float* __restrict__ fc2_b,   // [10]
                 float* __restrict__ out)           // [B,10]
{
    __shared__ float  feat[784];    // [patch*4 + q]
    __shared__ float  hidden[64];
    __shared__ float4 g[20];        // fused Ry*Rz*Ry per (layer,qubit): (a,b,c,d)

    const int b   = blockIdx.x;
    const int tid = threadIdx.x;

    // ---- Precompute fused SU(2) gates: U = Ry(p2)·Rz(p1)·Ry(p0)
    //   a =  cb*(cc*ca - sc*sa)   (Re u00)
    //   b = -sb*(cc*ca + sc*sa)   (Im u00)
    //   c = -cb*(cc*sa + sc*ca)   (Re u01)
    //   d =  sb*(cc*sa - sc*ca)   (Im u01)
    if (tid < 20) {
        const int L = tid >> 2, q = tid & 3;
        const float* p = weight + 12 * L;
        float ca, sa, cb, sb, cc, sc;
        sincosf(0.5f * p[q],     &sa, &ca);
        sincosf(0.5f * p[4 + q], &sb, &cb);
        sincosf(0.5f * p[8 + q], &sc, &cc);
        float t0 = cc * ca - sc * sa;
        float t1 = cc * ca + sc * sa;
        float t2 = cc * sa + sc * ca;
        float t3 = cc * sa - sc * ca;
        g[tid] = make_float4(cb * t0, -sb * t1, -cb * t2, sb * t3);
    }
    __syncthreads();

    if (tid < 196) {
        const int pi = tid / 14, pj = tid % 14;
        const float* xb = x + b * 784 + (2 * pi) * 28 + 2 * pj;
        const float2 xr0 = *reinterpret_cast<const float2*>(xb);
        const float2 xr1 = *reinterpret_cast<const float2*>(xb + 28);
        const float ang[4] = { xr0.x, xr0.y, xr1.x, xr1.y };

        // ---- Layer 0 fused with Rx encoding, applied to |0000>:
        // V_q = G0_q · Rx(2*pi*x_q). State = tensor product of first columns of V_q.
        // column: col0 = va + i vb ; col1 = -vc + i vd
        const float PI = 3.14159265358979323846f;
        float c0r[4], c0i[4], c1r[4], c1i[4];
#pragma unroll
        for (int q = 0; q < 4; q++) {
            float sx, cx;
            sincosf(PI * ang[q], &sx, &cx);
            float4 G = g[q];
            float va = G.x * cx + G.w * sx;
            float vb = G.y * cx - G.z * sx;
            float vc = G.z * cx + G.y * sx;
            float vd = G.w * cx - G.x * sx;
            c0r[q] = va;  c0i[q] = vb;
            c1r[q] = -vc; c1i[q] = vd;
        }

        float re[16], im[16];
        {
            // q0 (x) q1 -> 4 amplitudes indexed b0*2+b1
            float t2r[4], t2i[4];
#pragma unroll
            for (int b0 = 0; b0 < 2; b0++) {
                float ar = b0 ? c1r[0] : c0r[0], ai = b0 ? c1i[0] : c0i[0];
#pragma unroll
                for (int b1 = 0; b1 < 2; b1++) {
                    float br = b1 ? c1r[1] : c0r[1], bi = b1 ? c1i[1] : c0i[1];
                    t2r[b0 * 2 + b1] = ar * br - ai * bi;
                    t2i[b0 * 2 + b1] = ar * bi + ai * br;
                }
            }
            // (x) q2 -> 8
            float t3r[8], t3i[8];
#pragma unroll
            for (int m = 0; m < 4; m++) {
#pragma unroll
                for (int b2 = 0; b2 < 2; b2++) {
                    float br = b2 ? c1r[2] : c0r[2], bi = b2 ? c1i[2] : c0i[2];
                    t3r[m * 2 + b2] = t2r[m] * br - t2i[m] * bi;
                    t3i[m * 2 + b2] = t2r[m] * bi + t2i[m] * br;
                }
            }
            // (x) q3 -> 16
#pragma unroll
            for (int m = 0; m < 8; m++) {
#pragma unroll
                for (int b3 = 0; b3 < 2; b3++) {
                    float br = b3 ? c1r[3] : c0r[3], bi = b3 ? c1i[3] : c0i[3];
                    re[m * 2 + b3] = t3r[m] * br - t3i[m] * bi;
                    im[m * 2 + b3] = t3r[m] * bi + t3i[m] * br;
                }
            }
        }

        // ---- Layers 1..4: CNOT ring, then 4 fused gates
#pragma unroll
        for (int layer = 1; layer < 5; layer++) {
            apply_cnot(re, im, 8, 4);  // CNOT(0,1)
            apply_cnot(re, im, 4, 2);  // CNOT(1,2)
            apply_cnot(re, im, 2, 1);  // CNOT(2,3)
            apply_cnot(re, im, 1, 8);  // CNOT(3,0)
#pragma unroll
            for (int q = 0; q < 4; q++) {
                float4 G = g[layer * 4 + q];
                apply_su2(re, im, 8 >> q, G.x, G.y, G.z, G.w);
            }
        }

        // ---- <Z_q> expectations
        float e0 = 0.f, e1 = 0.f, e2 = 0.f, e3 = 0.f;
#pragma unroll
        for (int k = 0; k < 16; k++) {
            float p = re[k] * re[k] + im[k] * im[k];
            e0 += (k & 8) ? -p : p;
            e1 += (k & 4) ? -p : p;
            e2 += (k & 2) ? -p : p;
            e3 += (k & 1) ? -p : p;
        }
        feat[tid * 4 + 0] = e0;
        feat[tid * 4 + 1] = e1;
        feat[tid * 4 + 2] = e2;
        feat[tid * 4 + 3] = e3;
    }
    __syncthreads();

    // ---- FC1: hidden[h] = relu(feat . fc1_w[h,:] + fc1_b[h])
    {
        const int warp = tid >> 5;
        const int lane = tid & 31;
        const float4* W4 = reinterpret_cast<const float4*>(fc1_w);
        const float4* F4 = reinterpret_cast<const float4*>(feat);
        for (int h = warp; h < 64; h += NWARPS) {
            float acc = 0.f;
            for (int kk = lane; kk < 196; kk += 32) {
                float4 w = W4[h * 196 + kk];
                float4 f = F4[kk];
                acc += w.x * f.x + w.y * f.y + w.z * f.z + w.w * f.w;
            }
#pragma unroll
            for (int off = 16; off; off >>= 1)
                acc += __shfl_down_sync(0xffffffffu, acc, off);
            if (lane == 0)
                hidden[h] = fmaxf(acc + fc1_b[h], 0.f);
        }
    }
    __syncthreads();

    // ---- FC2: out[b, o] = hidden . fc2_w[o,:] + fc2_b[o]
    if (tid < 10) {
        float acc = fc2_b[tid];
#pragma unroll 8
        for (int h = 0; h < 64; h++)
            acc += hidden[h] * fc2_w[tid * 64 + h];
        out[b * 10 + tid] = acc;
    }
}

extern "C" void kernel_launch(void* const* d_in, const int* in_sizes, int n_in,
                              void* d_out, int out_size) {
    const float* x     = (const float*)d_in[0];
    const float* w     = (const float*)d_in[1];
    const float* fc1_w = (const float*)d_in[2];
    const float* fc1_b = (const float*)d_in[3];
    const float* fc2_w = (const float*)d_in[4];
    const float* fc2_b = (const float*)d_in[5];
    float* out = (float*)d_out;

    const int B = in_sizes[0] / 784;  // 128
    qnet_kernel<<<B, THREADS>>>(x, w, fc1_w, fc1_b, fc2_w, fc2_b, out);
}

// round 8
// speedup vs baseline: 1.8431x; 1.8431x over previous
#include <cuda_runtime.h>

#define THREADS 448   // 14 warps; threads 0..391 = 196 patches x 2 sub-threads
#define NWARPS 14

// Per-thread state: 8 complex amplitudes indexed m = (b0<<2)|(b1<<1)|b2.
// Qubit 3's bit is the thread's `sub` (tid & 1). Partner = tid ^ 1 (same warp).

// SU(2) gate [[a+ib, c+id],[-c+id, a-ib]] on a LOCAL qubit (mask in {4,2,1}).
__device__ __forceinline__ void su2_local(float* re, float* im, int mask,
                                          float a, float b, float c, float d) {
#pragma unroll
    for (int i = 0; i < 8; i++) {
        if (i & mask) continue;
        int j = i | mask;
        float r0 = re[i], i0 = im[i], r1 = re[j], i1 = im[j];
        re[i] =  a * r0 - b * i0 + c * r1 - d * i1;
        im[i] =  a * i0 + b * r0 + c * i1 + d * r1;
        re[j] = -c * r0 - d * i0 + a * r1 + b * i1;
        im[j] = -c * i0 + d * r0 + a * i1 - b * r1;
    }
}

// SU(2) on the SPLIT qubit (q3). Partner thread holds the other half.
// Uniform code via sign-folded coefficients: e = sub ? -b : b, f = sub ? -c : c.
__device__ __forceinline__ void su2_split(float* re, float* im, int sub,
                                          float a, float b, float c, float d) {
    const float e = sub ? -b : b;
    const float f = sub ? -c : c;
#pragma unroll
    for (int m = 0; m < 8; m++) {
        float pr = __shfl_xor_sync(0xffffffffu, re[m], 1);
        float pi = __shfl_xor_sync(0xffffffffu, im[m], 1);
        float r = re[m], i = im[m];
        re[m] = a * r - e * i + f * pr - d * pi;
        im[m] = a * i + e * r + f * pi + d * pr;
    }
}

__device__ __forceinline__ void lswap(float* re, float* im, int i, int j) {
    float t;
    t = re[i]; re[i] = re[j]; re[j] = t;
    t = im[i]; im[i] = im[j]; im[j] = t;
}

__global__ __launch_bounds__(THREADS, 1)
void qnet_kernel(const float* __restrict__ x,       // [B,1,28,28]
                 const float* __restrict__ weight,  // [60]
                 const float* __restrict__ fc1_w,   // [64,784]
                 const float* __restrict__ fc1_b,   // [64]
                 const float* __restrict__ fc2_w,   // [10,64]
                 const float* __restrict__ fc2_b,   // [10]
                 float* __restrict__ out)           // [B,10]
{
    __shared__ float  feat[784];    // [patch*4 + q]
    __shared__ float  hidden[64];
    __shared__ float4 g[20];        // fused Ry*Rz*Ry per (layer,qubit): (a,b,c,d)

    const int b   = blockIdx.x;
    const int tid = threadIdx.x;

    // ---- Precompute fused SU(2) gates: U = Ry(p2)*Rz(p1)*Ry(p0)
    if (tid < 20) {
        const int L = tid >> 2, q = tid & 3;
        const float* p = weight + 12 * L;
        float ca, sa, cb, sb, cc, sc;
        sincosf(0.5f * p[q],     &sa, &ca);
        sincosf(0.5f * p[4 + q], &sb, &cb);
        sincosf(0.5f * p[8 + q], &sc, &cc);
        float t0 = cc * ca - sc * sa;
        float t1 = cc * ca + sc * sa;
        float t2 = cc * sa + sc * ca;
        float t3 = cc * sa - sc * ca;
        g[tid] = make_float4(cb * t0, -sb * t1, -cb * t2, sb * t3);
    }
    __syncthreads();

    // ---- Circuit: 2 threads per patch; all warps fully converged (dummy work
    // for tid >= 392 on a clamped patch index; they just don't write feat).
    {
        const int p_raw = tid >> 1;
        const bool valid = p_raw < 196;
        const int p   = valid ? p_raw : 195;
        const int sub = tid & 1;                 // this thread's qubit-3 bit

        const int pi_ = p / 14, pj = p % 14;
        const float* xb = x + b * 784 + (2 * pi_) * 28 + 2 * pj;
        const float2 xr0 = *reinterpret_cast<const float2*>(xb);
        const float2 xr1 = *reinterpret_cast<const float2*>(xb + 28);
        const float ang[4] = { xr0.x, xr0.y, xr1.x, xr1.y };

        // Layer 0 fused with Rx encoding on |0000>: per qubit q,
        // V_q = G0_q * Rx(2*pi*x_q); state column entries:
        //   row0 = (a*cx + d*sx) + i(b*cx - c*sx)
        //   row1 = (-(c*cx + b*sx)) + i(d*cx - a*sx)
        const float PI = 3.14159265358979323846f;
        float r0c[3], i0c[3], r1c[3], i1c[3];   // qubits 0..2, both rows
        float v3r, v3i;                          // qubit 3, own row only
#pragma unroll
        for (int q = 0; q < 4; q++) {
            float sx, cx;
            sincosf(PI * ang[q], &sx, &cx);
            float4 G = g[q];
            float a0r =  G.x * cx + G.w * sx;
            float a0i =  G.y * cx - G.z * sx;
            float a1r = -(G.z * cx + G.y * sx);
            float a1i =  G.w * cx - G.x * sx;
            if (q < 3) {
                r0c[q] = a0r; i0c[q] = a0i;
                r1c[q] = a1r; i1c[q] = a1i;
            } else {
                v3r = sub ? a1r : a0r;
                v3i = sub ? a1i : a0i;
            }
        }

        float re[8], im[8];
        {
            // q0 (x) q1 -> 4 amplitudes
            float t2r[4], t2i[4];
#pragma unroll
            for (int b0 = 0; b0 < 2; b0++) {
                float ar = b0 ? r1c[0] : r0c[0], ai = b0 ? i1c[0] : i0c[0];
#pragma unroll
                for (int b1 = 0; b1 < 2; b1++) {
                    float br = b1 ? r1c[1] : r0c[1], bi = b1 ? i1c[1] : i0c[1];
                    t2r[b0 * 2 + b1] = ar * br - ai * bi;
                    t2i[b0 * 2 + b1] = ar * bi + ai * br;
                }
            }
            // fold q3 component into q2 column, then (x) q2 -> 8
            float B0r = r0c[2] * v3r - i0c[2] * v3i;
            float B0i = r0c[2] * v3i + i0c[2] * v3r;
            float B1r = r1c[2] * v3r - i1c[2] * v3i;
            float B1i = r1c[2] * v3i + i1c[2] * v3r;
#pragma unroll
            for (int m = 0; m < 4; m++) {
#pragma unroll
                for (int b2 = 0; b2 < 2; b2++) {
                    float br = b2 ? B1r : B0r, bi = b2 ? B1i : B0i;
                    re[m * 2 + b2] = t2r[m] * br - t2i[m] * bi;
                    im[m * 2 + b2] = t2r[m] * bi + t2i[m] * br;
                }
            }
        }

        // ---- Layers 1..4: CNOT ring, then fused gates
#pragma unroll
        for (int layer = 1; layer < 5; layer++) {
            // CNOT(0,1): control m&4, target m&2 -> swap (4,6),(5,7)
            lswap(re, im, 4, 6); lswap(re, im, 5, 7);
            // CNOT(1,2): control m&2, target m&1 -> swap (2,3),(6,7)
            lswap(re, im, 2, 3); lswap(re, im, 6, 7);
            // CNOT(2,3): control m&1, target = split bit -> exchange with partner
#pragma unroll
            for (int m = 1; m < 8; m += 2) {
                re[m] = __shfl_xor_sync(0xffffffffu, re[m], 1);
                im[m] = __shfl_xor_sync(0xffffffffu, im[m], 1);
            }
            // CNOT(3,0): control = split bit, target m&4 -> sub==1 swaps (m, m^4)
#pragma unroll
            for (int i = 0; i < 4; i++) {
                int j = i | 4;
                float nri = sub ? re[j] : re[i];
                float nrj = sub ? re[i] : re[j];
                float nii = sub ? im[j] : im[i];
                float nij = sub ? im[i] : im[j];
                re[i] = nri; re[j] = nrj; im[i] = nii; im[j] = nij;
            }
            // fused gates
            {
                float4 G;
                G = g[layer * 4 + 0]; su2_local(re, im, 4, G.x, G.y, G.z, G.w);
                G = g[layer * 4 + 1]; su2_local(re, im, 2, G.x, G.y, G.z, G.w);
                G = g[layer * 4 + 2]; su2_local(re, im, 1, G.x, G.y, G.z, G.w);
                G = g[layer * 4 + 3]; su2_split(re, im, sub, G.x, G.y, G.z, G.w);
            }
        }

        // ---- <Z_q> partials, then combine with partner
        float e0 = 0.f, e1 = 0.f, e2 = 0.f, e3 = 0.f;
#pragma unroll
        for (int m = 0; m < 8; m++) {
            float pr = re[m] * re[m] + im[m] * im[m];
            e0 += (m & 4) ? -pr : pr;
            e1 += (m & 2) ? -pr : pr;
            e2 += (m & 1) ? -pr : pr;
            e3 += sub ? -pr : pr;
        }
        e0 += __shfl_xor_sync(0xffffffffu, e0, 1);
        e1 += __shfl_xor_sync(0xffffffffu, e1, 1);
        e2 += __shfl_xor_sync(0xffffffffu, e2, 1);
        e3 += __shfl_xor_sync(0xffffffffu, e3, 1);

        if (valid && sub == 0) {
            feat[p * 4 + 0] = e0;
            feat[p * 4 + 1] = e1;
            feat[p * 4 + 2] = e2;
            feat[p * 4 + 3] = e3;
        }
    }
    __syncthreads();

    // ---- FC1: hidden[h] = relu(feat . fc1_w[h,:] + fc1_b[h]), one h per warp
    {
        const int warp = tid >> 5;
        const int lane = tid & 31;
        const float4* W4 = reinterpret_cast<const float4*>(fc1_w);
        const float4* F4 = reinterpret_cast<const float4*>(feat);
        for (int h = warp; h < 64; h += NWARPS) {
            float acc = 0.f;
            for (int kk = lane; kk < 196; kk += 32) {
                float4 w = W4[h * 196 + kk];
                float4 f = F4[kk];
                acc += w.x * f.x + w.y * f.y + w.z * f.z + w.w * f.w;
            }
#pragma unroll
            for (int off = 16; off; off >>= 1)
                acc += __shfl_down_sync(0xffffffffu, acc, off);
            if (lane == 0)
                hidden[h] = fmaxf(acc + fc1_b[h], 0.f);
        }
    }
    __syncthreads();

    // ---- FC2
    if (tid < 10) {
        float acc = fc2_b[tid];
#pragma unroll 8
        for (int h = 0; h < 64; h++)
            acc += hidden[h] * fc2_w[tid * 64 + h];
        out[b * 10 + tid] = acc;
    }
}

extern "C" void kernel_launch(void* const* d_in, const int* in_sizes, int n_in,
                              void* d_out, int out_size) {
    const float* x     = (const float*)d_in[0];
    const float* w     = (const float*)d_in[1];
    const float* fc1_w = (const float*)d_in[2];
    const float* fc1_b = (const float*)d_in[3];
    const float* fc2_w = (const float*)d_in[4];
    const float* fc2_b = (const float*)d_in[5];
    float* out = (float*)d_out;

    const int B = in_sizes[0] / 784;  // 128
    qnet_kernel<<<B, THREADS>>>(x, w, fc1_w, fc1_b, fc2_w, fc2_b, out);
}